// round 2
// baseline (speedup 1.0000x reference)
#include <cuda_runtime.h>
#include <cuda_bf16.h>
#include <cstdint>
#include <cstddef>

// LSTM layer: T=2048, B=64, I=512, H=512, fp32.
//   outputs[T,B,H], then h_T[B,H], then c_T[B,H] concatenated in d_out.
// Kernel A: gates_x[t*B+b, n] = sum_k inp[t,b,k]*W_ih[n,k] + b_ih[n] + b_hh[n]
// Kernel B: persistent recurrence, 128 CTAs (1/SM), grid barrier per step.

#define TSTEPS 2048
#define BATCH  64
#define IDIM   512
#define HDIM   512
#define NGATE  2048                    // 4*H
#define MROWS  (TSTEPS * BATCH)        // 131072
#define NBLK   128

__device__ float    g_gates[(size_t)MROWS * NGATE];  // 1 GiB scratch
__device__ float    g_hbuf[2][BATCH * HDIM];
__device__ unsigned g_bar;

__global__ void init_bar_kernel() { g_bar = 0u; }

// ---------------------------------------------------------------------------
// Kernel A: 128x128x16 tiled fp32 GEMM with f32x2 packed FMA.
// ---------------------------------------------------------------------------
#define BM 128
#define BN 128
#define BK 16

__global__ __launch_bounds__(256)
void gemm_gates_x(const float* __restrict__ A,     // [M, 512] = inp flattened
                  const float* __restrict__ W,     // [2048, 512] = W_ih
                  const float* __restrict__ bih,
                  const float* __restrict__ bhh)
{
    __shared__ float As[BK][BM + 4];
    __shared__ float Bs[BK][BN + 4];

    const int tid = threadIdx.x;
    const int tm  = tid >> 4;        // 0..15
    const int tn  = tid & 15;        // 0..15
    const int m0  = blockIdx.y * BM;
    const int n0  = blockIdx.x * BN;

    unsigned long long acc[4][8];
#pragma unroll
    for (int p = 0; p < 4; p++)
#pragma unroll
        for (int j = 0; j < 8; j++) acc[p][j] = 0ULL;

    const int lrow = tid >> 2;        // 0..63
    const int lc4  = (tid & 3) * 4;   // 0,4,8,12

    for (int k0 = 0; k0 < IDIM; k0 += BK) {
#pragma unroll
        for (int h = 0; h < 2; h++) {
            const int r = lrow + h * 64;
            float4 va = *(const float4*)&A[(size_t)(m0 + r) * IDIM + k0 + lc4];
            As[lc4 + 0][r] = va.x; As[lc4 + 1][r] = va.y;
            As[lc4 + 2][r] = va.z; As[lc4 + 3][r] = va.w;
            float4 vb = *(const float4*)&W[(size_t)(n0 + r) * IDIM + k0 + lc4];
            Bs[lc4 + 0][r] = vb.x; Bs[lc4 + 1][r] = vb.y;
            Bs[lc4 + 2][r] = vb.z; Bs[lc4 + 3][r] = vb.w;
        }
        __syncthreads();

#pragma unroll
        for (int k = 0; k < BK; k++) {
            float4 a0 = *(const float4*)&As[k][tm * 4];
            float4 a1 = *(const float4*)&As[k][tm * 4 + 64];
            float4 b0 = *(const float4*)&Bs[k][tn * 4];
            float4 b1 = *(const float4*)&Bs[k][tn * 4 + 64];
            unsigned long long a2[4];
            a2[0] = *(unsigned long long*)&a0.x;
            a2[1] = *(unsigned long long*)&a0.z;
            a2[2] = *(unsigned long long*)&a1.x;
            a2[3] = *(unsigned long long*)&a1.z;
            float bs[8] = {b0.x, b0.y, b0.z, b0.w, b1.x, b1.y, b1.z, b1.w};
#pragma unroll
            for (int j = 0; j < 8; j++) {
                unsigned long long b2;
                asm("mov.b64 %0,{%1,%1};" : "=l"(b2) : "r"(__float_as_uint(bs[j])));
#pragma unroll
                for (int p = 0; p < 4; p++)
                    asm("fma.rn.f32x2 %0,%1,%2,%0;"
                        : "+l"(acc[p][j]) : "l"(a2[p]), "l"(b2));
            }
        }
        __syncthreads();
    }

    // epilogue: + (b_ih + b_hh), write float4 per row / col-group
    const int nlo = n0 + tn * 4;
    const int nhi = nlo + 64;
    float4 t1 = *(const float4*)&bih[nlo];
    float4 t2 = *(const float4*)&bhh[nlo];
    float4 blo = make_float4(t1.x + t2.x, t1.y + t2.y, t1.z + t2.z, t1.w + t2.w);
    t1 = *(const float4*)&bih[nhi];
    t2 = *(const float4*)&bhh[nhi];
    float4 bhi = make_float4(t1.x + t2.x, t1.y + t2.y, t1.z + t2.z, t1.w + t2.w);

#pragma unroll
    for (int p = 0; p < 4; p++) {
        const int prbase = (p < 2) ? (tm * 4 + 2 * p) : (64 + tm * 4 + 2 * (p - 2));
#pragma unroll
        for (int h = 0; h < 2; h++) {
            const size_t m = (size_t)(m0 + prbase + h);
            float4 vlo, vhi;
            {
                float2 f0 = *(float2*)&acc[p][0];
                float2 f1 = *(float2*)&acc[p][1];
                float2 f2 = *(float2*)&acc[p][2];
                float2 f3 = *(float2*)&acc[p][3];
                vlo = make_float4(h ? f0.y : f0.x, h ? f1.y : f1.x,
                                  h ? f2.y : f2.x, h ? f3.y : f3.x);
                float2 g0 = *(float2*)&acc[p][4];
                float2 g1 = *(float2*)&acc[p][5];
                float2 g2 = *(float2*)&acc[p][6];
                float2 g3 = *(float2*)&acc[p][7];
                vhi = make_float4(h ? g0.y : g0.x, h ? g1.y : g1.x,
                                  h ? g2.y : g2.x, h ? g3.y : g3.x);
            }
            vlo.x += blo.x; vlo.y += blo.y; vlo.z += blo.z; vlo.w += blo.w;
            vhi.x += bhi.x; vhi.y += bhi.y; vhi.z += bhi.z; vhi.w += bhi.w;
            *(float4*)&g_gates[m * NGATE + nlo] = vlo;
            *(float4*)&g_gates[m * NGATE + nhi] = vhi;
        }
    }
}

// ---------------------------------------------------------------------------
// Kernel B: persistent recurrence
// ---------------------------------------------------------------------------
__device__ __forceinline__ float fsig(float x) {
    return __fdividef(1.0f, 1.0f + __expf(-x));
}
__device__ __forceinline__ float ftanh(float x) {
    x = fminf(fmaxf(x, -15.0f), 15.0f);
    float e = __expf(-2.0f * x);
    return __fdividef(1.0f - e, 1.0f + e);
}

// SMEM layout (floats): W_s 32 rows x 516 stride (16512), then h_s 32x512 (16384)
#define WS_FLOATS 16512
#define HS_FLOATS 16384
#define SMEM_B_BYTES ((WS_FLOATS + HS_FLOATS) * 4)   // 131584

__global__ __launch_bounds__(256, 1)
void lstm_rec(const float* __restrict__ h0,
              const float* __restrict__ c0,
              const float* __restrict__ Whh,
              float* __restrict__ out)
{
    extern __shared__ float sm[];
    float4* W_s4 = (float4*)sm;                 // stride 129 float4 per row
    float4* h_s4 = (float4*)(sm + WS_FLOATS);   // stride 128 float4, rotated

    const int tid  = threadIdx.x;
    const int cb   = blockIdx.x;
    const int b0   = (cb & 1) * 32;             // batch tile base
    const int j0   = (cb >> 1) * 8;             // hidden tile base
    const int w    = tid >> 5, lane = tid & 31;
    const int wb   = w & 1, wj = w >> 1;        // warp: batch-half, j-pair
    const int lb   = lane & 15, lj = lane >> 4;
    const int bl   = wb * 16 + lb;              // local batch 0..31
    const int b    = b0 + bl;
    const int jj   = wj * 2 + lj;               // local j 0..7
    const int j    = j0 + jj;

    // Stage W_hh slice once: rows rr = g*8 + jj_row -> global row g*512 + j0 + jj_row
    const float4* Whh4 = (const float4*)Whh;
#pragma unroll
    for (int i = 0; i < 16; i++) {
        int idx = tid + i * 256;
        int rr = idx >> 7, c = idx & 127;
        int R = (rr >> 3) * HDIM + j0 + (rr & 7);
        W_s4[rr * 129 + c] = Whh4[(size_t)R * 128 + c];
    }

    float c_reg  = c0[b * HDIM + j];
    float h_last = 0.0f;

    const unsigned hbase = (unsigned)__cvta_generic_to_shared(h_s4 + (size_t)bl * 128);
    const unsigned wbase = (unsigned)__cvta_generic_to_shared(W_s4 + (size_t)jj * 129);
    unsigned long long barp = (unsigned long long)__cvta_generic_to_global(&g_bar);

    for (int t = 0; t < TSTEPS; t++) {
        // prefetch gx for this thread's 4 gates (consumed after dot loop)
        const float* gxp = g_gates + (size_t)(t * BATCH + b) * NGATE + j;
        float gx0 = __ldcs(gxp);
        float gx1 = __ldcs(gxp + 512);
        float gx2 = __ldcs(gxp + 1024);
        float gx3 = __ldcs(gxp + 1536);

        // stage h for this CTA's 32 batches into swizzled smem
        const float4* hsrc = (t == 0) ? ((const float4*)h0 + (size_t)b0 * 128)
                                      : ((const float4*)g_hbuf[t & 1] + (size_t)b0 * 128);
#pragma unroll
        for (int i = 0; i < 16; i++) {
            int idx = tid + i * 256;
            int rbl = idx >> 7, c = idx & 127;
            h_s4[rbl * 128 + ((c + rbl) & 127)] = hsrc[rbl * 128 + c];
        }
        __syncthreads();

        // 4 dot products of length 512 (gates i,f,g,o at this (b,j))
        unsigned long long acc0 = 0, acc1 = 0, acc2 = 0, acc3 = 0;
#pragma unroll 4
        for (int c = 0; c < 128; c++) {
            unsigned haddr = hbase + (((c + bl) & 127) << 4);
            unsigned waddr = wbase + (c << 4);
            unsigned long long h2a, h2b, w2a, w2b;
            asm("ld.shared.v2.b64 {%0,%1},[%2];" : "=l"(h2a), "=l"(h2b) : "r"(haddr));
            asm("ld.shared.v2.b64 {%0,%1},[%2];" : "=l"(w2a), "=l"(w2b) : "r"(waddr));
            asm("fma.rn.f32x2 %0,%1,%2,%0;" : "+l"(acc0) : "l"(h2a), "l"(w2a));
            asm("fma.rn.f32x2 %0,%1,%2,%0;" : "+l"(acc0) : "l"(h2b), "l"(w2b));
            asm("ld.shared.v2.b64 {%0,%1},[%2+16512];" : "=l"(w2a), "=l"(w2b) : "r"(waddr));
            asm("fma.rn.f32x2 %0,%1,%2,%0;" : "+l"(acc1) : "l"(h2a), "l"(w2a));
            asm("fma.rn.f32x2 %0,%1,%2,%0;" : "+l"(acc1) : "l"(h2b), "l"(w2b));
            asm("ld.shared.v2.b64 {%0,%1},[%2+33024];" : "=l"(w2a), "=l"(w2b) : "r"(waddr));
            asm("fma.rn.f32x2 %0,%1,%2,%0;" : "+l"(acc2) : "l"(h2a), "l"(w2a));
            asm("fma.rn.f32x2 %0,%1,%2,%0;" : "+l"(acc2) : "l"(h2b), "l"(w2b));
            asm("ld.shared.v2.b64 {%0,%1},[%2+49536];" : "=l"(w2a), "=l"(w2b) : "r"(waddr));
            asm("fma.rn.f32x2 %0,%1,%2,%0;" : "+l"(acc3) : "l"(h2a), "l"(w2a));
            asm("fma.rn.f32x2 %0,%1,%2,%0;" : "+l"(acc3) : "l"(h2b), "l"(w2b));
        }

        float2 f0 = *(float2*)&acc0;
        float2 f1 = *(float2*)&acc1;
        float2 f2 = *(float2*)&acc2;
        float2 f3 = *(float2*)&acc3;
        float gi = fsig (gx0 + f0.x + f0.y);
        float gf = fsig (gx1 + f1.x + f1.y);
        float gg = ftanh(gx2 + f2.x + f2.y);
        float go = fsig (gx3 + f3.x + f3.y);
        c_reg  = gf * c_reg + gi * gg;
        h_last = go * ftanh(c_reg);

        out[(size_t)t * (BATCH * HDIM) + b * HDIM + j] = h_last;
        g_hbuf[(t + 1) & 1][b * HDIM + j] = h_last;

        // grid barrier (release/acquire, monotonic counter, reset by init kernel)
        __syncthreads();
        if (tid == 0) {
            __threadfence();
            asm volatile("red.release.gpu.global.add.u32 [%0], %1;"
                         :: "l"(barp), "r"(1u) : "memory");
            const unsigned target = (unsigned)(t + 1) * NBLK;
            unsigned v;
            do {
                asm volatile("ld.acquire.gpu.global.u32 %0, [%1];"
                             : "=r"(v) : "l"(barp) : "memory");
            } while (v < target);
        }
        __syncthreads();
    }

    // final states
    out[(size_t)TSTEPS * (BATCH * HDIM) + b * HDIM + j] = h_last;
    out[(size_t)TSTEPS * (BATCH * HDIM) + BATCH * HDIM + b * HDIM + j] = c_reg;
}

// ---------------------------------------------------------------------------
extern "C" void kernel_launch(void* const* d_in, const int* in_sizes, int n_in,
                              void* d_out, int out_size) {
    const float* inp = (const float*)d_in[0];   // [T, B, I]
    const float* h0  = (const float*)d_in[1];   // [B, H]
    const float* c0  = (const float*)d_in[2];   // [B, H]
    const float* Wih = (const float*)d_in[3];   // [4H, I]
    const float* Whh = (const float*)d_in[4];   // [4H, H]
    const float* bih = (const float*)d_in[5];   // [4H]
    const float* bhh = (const float*)d_in[6];   // [4H]
    float* out = (float*)d_out;

    cudaFuncSetAttribute(lstm_rec, cudaFuncAttributeMaxDynamicSharedMemorySize,
                         SMEM_B_BYTES);

    dim3 gridA(NGATE / BN, MROWS / BM);   // (16, 1024)
    gemm_gates_x<<<gridA, 256>>>(inp, Wih, bih, bhh);
    init_bar_kernel<<<1, 1>>>();
    lstm_rec<<<NBLK, 256, SMEM_B_BYTES>>>(h0, c0, Whh, out);
}

// round 3
// speedup vs baseline: 1.1078x; 1.1078x over previous
#include <cuda_runtime.h>
#include <cuda_bf16.h>
#include <cstdint>
#include <cstddef>

// LSTM layer: T=2048, B=64, I=512, H=512, fp32.
//   d_out = outputs[T,B,H] ++ h_T[B,H] ++ c_T[B,H]
// Kernel A: gates_x = inp @ W_ih^T + b_ih + b_hh  (1 GiB device scratch)
// Kernel B: persistent recurrence, 128 CTAs (1/SM), 128 thr/CTA,
//           each thread owns 2 (batch) cells -> FMA-bound dot loop.

#define TSTEPS 2048
#define BATCH  64
#define IDIM   512
#define HDIM   512
#define NGATE  2048
#define MROWS  (TSTEPS * BATCH)
#define NBLK   128

__device__ float    g_gates[(size_t)MROWS * NGATE];
__device__ float    g_hbuf[2][BATCH * HDIM];
__device__ unsigned g_bar;

__global__ void init_bar_kernel() { g_bar = 0u; }

// ---------------------------------------------------------------------------
// Kernel A: 128x128x16 tiled fp32 GEMM with f32x2 packed FMA. (unchanged, near peak)
// ---------------------------------------------------------------------------
#define BM 128
#define BN 128
#define BK 16

__global__ __launch_bounds__(256)
void gemm_gates_x(const float* __restrict__ A,
                  const float* __restrict__ W,
                  const float* __restrict__ bih,
                  const float* __restrict__ bhh)
{
    __shared__ float As[BK][BM + 4];
    __shared__ float Bs[BK][BN + 4];

    const int tid = threadIdx.x;
    const int tm  = tid >> 4;
    const int tn  = tid & 15;
    const int m0  = blockIdx.y * BM;
    const int n0  = blockIdx.x * BN;

    unsigned long long acc[4][8];
#pragma unroll
    for (int p = 0; p < 4; p++)
#pragma unroll
        for (int j = 0; j < 8; j++) acc[p][j] = 0ULL;

    const int lrow = tid >> 2;
    const int lc4  = (tid & 3) * 4;

    for (int k0 = 0; k0 < IDIM; k0 += BK) {
#pragma unroll
        for (int h = 0; h < 2; h++) {
            const int r = lrow + h * 64;
            float4 va = *(const float4*)&A[(size_t)(m0 + r) * IDIM + k0 + lc4];
            As[lc4 + 0][r] = va.x; As[lc4 + 1][r] = va.y;
            As[lc4 + 2][r] = va.z; As[lc4 + 3][r] = va.w;
            float4 vb = *(const float4*)&W[(size_t)(n0 + r) * IDIM + k0 + lc4];
            Bs[lc4 + 0][r] = vb.x; Bs[lc4 + 1][r] = vb.y;
            Bs[lc4 + 2][r] = vb.z; Bs[lc4 + 3][r] = vb.w;
        }
        __syncthreads();

#pragma unroll
        for (int k = 0; k < BK; k++) {
            float4 a0 = *(const float4*)&As[k][tm * 4];
            float4 a1 = *(const float4*)&As[k][tm * 4 + 64];
            float4 b0 = *(const float4*)&Bs[k][tn * 4];
            float4 b1 = *(const float4*)&Bs[k][tn * 4 + 64];
            unsigned long long a2[4];
            a2[0] = *(unsigned long long*)&a0.x;
            a2[1] = *(unsigned long long*)&a0.z;
            a2[2] = *(unsigned long long*)&a1.x;
            a2[3] = *(unsigned long long*)&a1.z;
            float bs[8] = {b0.x, b0.y, b0.z, b0.w, b1.x, b1.y, b1.z, b1.w};
#pragma unroll
            for (int j = 0; j < 8; j++) {
                unsigned long long b2;
                asm("mov.b64 %0,{%1,%1};" : "=l"(b2) : "r"(__float_as_uint(bs[j])));
#pragma unroll
                for (int p = 0; p < 4; p++)
                    asm("fma.rn.f32x2 %0,%1,%2,%0;"
                        : "+l"(acc[p][j]) : "l"(a2[p]), "l"(b2));
            }
        }
        __syncthreads();
    }

    const int nlo = n0 + tn * 4;
    const int nhi = nlo + 64;
    float4 t1 = *(const float4*)&bih[nlo];
    float4 t2 = *(const float4*)&bhh[nlo];
    float4 blo = make_float4(t1.x + t2.x, t1.y + t2.y, t1.z + t2.z, t1.w + t2.w);
    t1 = *(const float4*)&bih[nhi];
    t2 = *(const float4*)&bhh[nhi];
    float4 bhi = make_float4(t1.x + t2.x, t1.y + t2.y, t1.z + t2.z, t1.w + t2.w);

#pragma unroll
    for (int p = 0; p < 4; p++) {
        const int prbase = (p < 2) ? (tm * 4 + 2 * p) : (64 + tm * 4 + 2 * (p - 2));
#pragma unroll
        for (int h = 0; h < 2; h++) {
            const size_t m = (size_t)(m0 + prbase + h);
            float4 vlo, vhi;
            {
                float2 f0 = *(float2*)&acc[p][0];
                float2 f1 = *(float2*)&acc[p][1];
                float2 f2 = *(float2*)&acc[p][2];
                float2 f3 = *(float2*)&acc[p][3];
                vlo = make_float4(h ? f0.y : f0.x, h ? f1.y : f1.x,
                                  h ? f2.y : f2.x, h ? f3.y : f3.x);
                float2 g0 = *(float2*)&acc[p][4];
                float2 g1 = *(float2*)&acc[p][5];
                float2 g2 = *(float2*)&acc[p][6];
                float2 g3 = *(float2*)&acc[p][7];
                vhi = make_float4(h ? g0.y : g0.x, h ? g1.y : g1.x,
                                  h ? g2.y : g2.x, h ? g3.y : g3.x);
            }
            vlo.x += blo.x; vlo.y += blo.y; vlo.z += blo.z; vlo.w += blo.w;
            vhi.x += bhi.x; vhi.y += bhi.y; vhi.z += bhi.z; vhi.w += bhi.w;
            *(float4*)&g_gates[m * NGATE + nlo] = vlo;
            *(float4*)&g_gates[m * NGATE + nhi] = vhi;
        }
    }
}

// ---------------------------------------------------------------------------
// Kernel B: persistent recurrence, 128 threads/CTA, 2 batch-cells per thread.
// ---------------------------------------------------------------------------
__device__ __forceinline__ float fsig(float x) {
    return __fdividef(1.0f, 1.0f + __expf(-x));
}
__device__ __forceinline__ float ftanh(float x) {
    x = fminf(fmaxf(x, -15.0f), 15.0f);
    float e = __expf(-2.0f * x);
    return __fdividef(1.0f - e, 1.0f + e);
}

#define WS_FLOATS 16512           // 32 rows x 516 (stride 129 float4)
#define HS_FLOATS 16384           // 32 x 512
#define SMEM_B_BYTES ((WS_FLOATS + HS_FLOATS) * 4)   // 131584 -> 1 CTA/SM

__global__ __launch_bounds__(128, 1)
void lstm_rec(const float* __restrict__ h0,
              const float* __restrict__ c0,
              const float* __restrict__ Whh,
              float* __restrict__ out)
{
    extern __shared__ float sm[];
    float4* W_s4 = (float4*)sm;
    float4* h_s4 = (float4*)(sm + WS_FLOATS);

    const int tid  = threadIdx.x;           // 0..127
    const int cb   = blockIdx.x;
    const int b0   = (cb & 1) * 32;
    const int j0   = (cb >> 1) * 8;
    const int w    = tid >> 5;              // 0..3
    const int lane = tid & 31;
    const int lb   = lane & 15;             // batch slot 0..15
    const int lj   = lane >> 4;             // 0/1
    const int jj   = w * 2 + lj;            // 0..7
    const int j    = j0 + jj;
    const int b1   = b0 + lb;               // this thread's two batches
    const int b2   = b0 + lb + 16;

    // Stage W_hh slice once: row rr = g*8 + jr  <- global row g*512 + j0 + jr
    const float4* Whh4 = (const float4*)Whh;
#pragma unroll
    for (int i = 0; i < 32; i++) {
        int idx = tid + i * 128;
        int rr = idx >> 7, c = idx & 127;
        int R = (rr >> 3) * HDIM + j0 + (rr & 7);
        W_s4[rr * 129 + c] = Whh4[(size_t)R * 128 + c];
    }

    float c_reg1 = c0[b1 * HDIM + j];
    float c_reg2 = c0[b2 * HDIM + j];
    float h1v = 0.0f, h2v = 0.0f;

    const unsigned hbase1 = (unsigned)__cvta_generic_to_shared(h_s4 + (size_t)lb * 128);
    const unsigned hbase2 = (unsigned)__cvta_generic_to_shared(h_s4 + (size_t)(lb + 16) * 128);
    const unsigned wbase  = (unsigned)__cvta_generic_to_shared(W_s4 + (size_t)jj * 129);
    unsigned long long barp = (unsigned long long)__cvta_generic_to_global(&g_bar);

    for (int t = 0; t < TSTEPS; t++) {
        // prefetch gx for both cells (consumed after dot loop)
        const float* gxp1 = g_gates + (size_t)(t * BATCH + b1) * NGATE + j;
        const float* gxp2 = g_gates + (size_t)(t * BATCH + b2) * NGATE + j;
        float gx10 = __ldcs(gxp1);
        float gx11 = __ldcs(gxp1 + 512);
        float gx12 = __ldcs(gxp1 + 1024);
        float gx13 = __ldcs(gxp1 + 1536);
        float gx20 = __ldcs(gxp2);
        float gx21 = __ldcs(gxp2 + 512);
        float gx22 = __ldcs(gxp2 + 1024);
        float gx23 = __ldcs(gxp2 + 1536);

        // stage h for this CTA's 32 batches into rotated smem
        const float4* hsrc = (t == 0) ? ((const float4*)h0 + (size_t)b0 * 128)
                                      : ((const float4*)g_hbuf[t & 1] + (size_t)b0 * 128);
#pragma unroll
        for (int i = 0; i < 32; i++) {
            int idx = tid + i * 128;
            int rbl = idx >> 7, c = idx & 127;
            h_s4[rbl * 128 + ((c + rbl) & 127)] = hsrc[rbl * 128 + c];
        }
        __syncthreads();

        // 8 dot products of length 512: gates i,f,g,o for batches b1,b2
        unsigned long long a00 = 0, a01 = 0, a10 = 0, a11 = 0;
        unsigned long long a20 = 0, a21 = 0, a30 = 0, a31 = 0;
#pragma unroll 4
        for (int c = 0; c < 128; c++) {
            unsigned ha1 = hbase1 + (((c + lb) & 127) << 4);
            unsigned ha2 = hbase2 + (((c + lb + 16) & 127) << 4);
            unsigned wa  = wbase + (c << 4);
            unsigned long long h1a, h1b, h2a, h2b, wva, wvb;
            asm("ld.shared.v2.b64 {%0,%1},[%2];" : "=l"(h1a), "=l"(h1b) : "r"(ha1));
            asm("ld.shared.v2.b64 {%0,%1},[%2];" : "=l"(h2a), "=l"(h2b) : "r"(ha2));
            asm("ld.shared.v2.b64 {%0,%1},[%2];" : "=l"(wva), "=l"(wvb) : "r"(wa));
            asm("fma.rn.f32x2 %0,%1,%2,%0;" : "+l"(a00) : "l"(h1a), "l"(wva));
            asm("fma.rn.f32x2 %0,%1,%2,%0;" : "+l"(a00) : "l"(h1b), "l"(wvb));
            asm("fma.rn.f32x2 %0,%1,%2,%0;" : "+l"(a01) : "l"(h2a), "l"(wva));
            asm("fma.rn.f32x2 %0,%1,%2,%0;" : "+l"(a01) : "l"(h2b), "l"(wvb));
            asm("ld.shared.v2.b64 {%0,%1},[%2+16512];" : "=l"(wva), "=l"(wvb) : "r"(wa));
            asm("fma.rn.f32x2 %0,%1,%2,%0;" : "+l"(a10) : "l"(h1a), "l"(wva));
            asm("fma.rn.f32x2 %0,%1,%2,%0;" : "+l"(a10) : "l"(h1b), "l"(wvb));
            asm("fma.rn.f32x2 %0,%1,%2,%0;" : "+l"(a11) : "l"(h2a), "l"(wva));
            asm("fma.rn.f32x2 %0,%1,%2,%0;" : "+l"(a11) : "l"(h2b), "l"(wvb));
            asm("ld.shared.v2.b64 {%0,%1},[%2+33024];" : "=l"(wva), "=l"(wvb) : "r"(wa));
            asm("fma.rn.f32x2 %0,%1,%2,%0;" : "+l"(a20) : "l"(h1a), "l"(wva));
            asm("fma.rn.f32x2 %0,%1,%2,%0;" : "+l"(a20) : "l"(h1b), "l"(wvb));
            asm("fma.rn.f32x2 %0,%1,%2,%0;" : "+l"(a21) : "l"(h2a), "l"(wva));
            asm("fma.rn.f32x2 %0,%1,%2,%0;" : "+l"(a21) : "l"(h2b), "l"(wvb));
            asm("ld.shared.v2.b64 {%0,%1},[%2+49536];" : "=l"(wva), "=l"(wvb) : "r"(wa));
            asm("fma.rn.f32x2 %0,%1,%2,%0;" : "+l"(a30) : "l"(h1a), "l"(wva));
            asm("fma.rn.f32x2 %0,%1,%2,%0;" : "+l"(a30) : "l"(h1b), "l"(wvb));
            asm("fma.rn.f32x2 %0,%1,%2,%0;" : "+l"(a31) : "l"(h2a), "l"(wva));
            asm("fma.rn.f32x2 %0,%1,%2,%0;" : "+l"(a31) : "l"(h2b), "l"(wvb));
        }

        {
            float2 f;
            f = *(float2*)&a00; float gi1 = fsig (gx10 + f.x + f.y);
            f = *(float2*)&a10; float gf1 = fsig (gx11 + f.x + f.y);
            f = *(float2*)&a20; float gg1 = ftanh(gx12 + f.x + f.y);
            f = *(float2*)&a30; float go1 = fsig (gx13 + f.x + f.y);
            c_reg1 = gf1 * c_reg1 + gi1 * gg1;
            h1v    = go1 * ftanh(c_reg1);

            f = *(float2*)&a01; float gi2 = fsig (gx20 + f.x + f.y);
            f = *(float2*)&a11; float gf2 = fsig (gx21 + f.x + f.y);
            f = *(float2*)&a21; float gg2 = ftanh(gx22 + f.x + f.y);
            f = *(float2*)&a31; float go2 = fsig (gx23 + f.x + f.y);
            c_reg2 = gf2 * c_reg2 + gi2 * gg2;
            h2v    = go2 * ftanh(c_reg2);
        }

        out[(size_t)t * (BATCH * HDIM) + b1 * HDIM + j] = h1v;
        out[(size_t)t * (BATCH * HDIM) + b2 * HDIM + j] = h2v;
        g_hbuf[(t + 1) & 1][b1 * HDIM + j] = h1v;
        g_hbuf[(t + 1) & 1][b2 * HDIM + j] = h2v;

        __syncthreads();
        if (tid == 0) {
            __threadfence();
            asm volatile("red.release.gpu.global.add.u32 [%0], %1;"
                         :: "l"(barp), "r"(1u) : "memory");
            const unsigned target = (unsigned)(t + 1) * NBLK;
            unsigned v;
            do {
                asm volatile("ld.acquire.gpu.global.u32 %0, [%1];"
                             : "=r"(v) : "l"(barp) : "memory");
            } while (v < target);
        }
        __syncthreads();
    }

    const size_t obase = (size_t)TSTEPS * (BATCH * HDIM);
    out[obase + b1 * HDIM + j] = h1v;
    out[obase + b2 * HDIM + j] = h2v;
    out[obase + BATCH * HDIM + b1 * HDIM + j] = c_reg1;
    out[obase + BATCH * HDIM + b2 * HDIM + j] = c_reg2;
}

// ---------------------------------------------------------------------------
extern "C" void kernel_launch(void* const* d_in, const int* in_sizes, int n_in,
                              void* d_out, int out_size) {
    const float* inp = (const float*)d_in[0];
    const float* h0  = (const float*)d_in[1];
    const float* c0  = (const float*)d_in[2];
    const float* Wih = (const float*)d_in[3];
    const float* Whh = (const float*)d_in[4];
    const float* bih = (const float*)d_in[5];
    const float* bhh = (const float*)d_in[6];
    float* out = (float*)d_out;

    cudaFuncSetAttribute(lstm_rec, cudaFuncAttributeMaxDynamicSharedMemorySize,
                         SMEM_B_BYTES);

    dim3 gridA(NGATE / BN, MROWS / BM);
    gemm_gates_x<<<gridA, 256>>>(inp, Wih, bih, bhh);
    init_bar_kernel<<<1, 1>>>();
    lstm_rec<<<NBLK, 128, SMEM_B_BYTES>>>(h0, c0, Whh, out);
}